// round 1
// baseline (speedup 1.0000x reference)
#include <cuda_runtime.h>

// Problem constants
static constexpr int Bc = 2;
static constexpr int Sc = 2048;
static constexpr int Ec = 1024;
static constexpr int Hc = 16;
static constexpr int Dc = 64;   // head dim

// Scratch (allocation-free rule: __device__ globals)
__device__ float g_q[(size_t)Bc * Hc * Sc * Dc];    // (b,h,s,d)
__device__ float g_k[(size_t)Bc * Hc * Sc * Dc];    // (b,h,s,d)
__device__ float g_v[(size_t)Bc * Hc * Sc * Dc];    // (b,h,s,d)
__device__ float g_ctx[(size_t)Bc * Sc * Ec];       // (b,s,e) merged heads

// ---------------------------------------------------------------------------
// Generic C = A @ W^T * scale + bias.
// A: (M,K) row-major (row stride K). W: (N,K) row-major. Batched via blockIdx.z.
// BM=BN=128, BK=8, 256 threads, 8x8 per thread.
// HEADSPLIT: scatter C[m,n] -> (b,h,s,d) layout (used by Q/K/V projections).
// ---------------------------------------------------------------------------
template <bool HEADSPLIT>
__global__ __launch_bounds__(256, 2)
void gemm128_xwT(const float* __restrict__ A, const float* __restrict__ W,
                 const float* __restrict__ bias, float* __restrict__ C,
                 int M, int N, int K,
                 long sA, long sW, long sC, float scale)
{
    A += (long)blockIdx.z * sA;
    W += (long)blockIdx.z * sW;
    C += (long)blockIdx.z * sC;

    const int n0 = blockIdx.x * 128;
    const int m0 = blockIdx.y * 128;

    __shared__ float As[8][128];
    __shared__ float Bs[8][128];

    const int tid = threadIdx.x;
    const int tx  = tid & 15;   // 16 cols of 8
    const int ty  = tid >> 4;   // 16 rows of 8
    const int lr  = tid >> 1;           // load row 0..127
    const int lc  = (tid & 1) * 4;      // load col 0 or 4

    float acc[8][8];
#pragma unroll
    for (int i = 0; i < 8; i++)
#pragma unroll
        for (int j = 0; j < 8; j++) acc[i][j] = 0.0f;

    const float* Aptr = A + (long)(m0 + lr) * K + lc;
    const float* Wptr = W + (long)(n0 + lr) * K + lc;

    for (int kt = 0; kt < K; kt += 8) {
        float4 a = *(const float4*)(Aptr + kt);
        float4 b = *(const float4*)(Wptr + kt);
        As[lc + 0][lr] = a.x; As[lc + 1][lr] = a.y;
        As[lc + 2][lr] = a.z; As[lc + 3][lr] = a.w;
        Bs[lc + 0][lr] = b.x; Bs[lc + 1][lr] = b.y;
        Bs[lc + 2][lr] = b.z; Bs[lc + 3][lr] = b.w;
        __syncthreads();

#pragma unroll
        for (int k = 0; k < 8; k++) {
            float ra[8], rb[8];
#pragma unroll
            for (int i = 0; i < 8; i++) ra[i] = As[k][ty * 8 + i];
#pragma unroll
            for (int j = 0; j < 8; j++) rb[j] = Bs[k][tx * 8 + j];
#pragma unroll
            for (int i = 0; i < 8; i++)
#pragma unroll
                for (int j = 0; j < 8; j++)
                    acc[i][j] = fmaf(ra[i], rb[j], acc[i][j]);
        }
        __syncthreads();
    }

#pragma unroll
    for (int i = 0; i < 8; i++) {
        const int m = m0 + ty * 8 + i;
#pragma unroll
        for (int j = 0; j < 8; j++) {
            const int n = n0 + tx * 8 + j;
            float val = acc[i][j] * scale;
            if (bias) val += bias[n];
            if (HEADSPLIT) {
                const int b = m >> 11;          // m / Sc (Sc = 2048)
                const int s = m & (Sc - 1);
                const int h = n >> 6;           // n / Dc (Dc = 64)
                const int d = n & (Dc - 1);
                C[(((long)b * Hc + h) * Sc + s) * Dc + d] = val;
            } else {
                C[(long)m * N + n] = val;
            }
        }
    }
}

// ---------------------------------------------------------------------------
// Row softmax in place: B*H*S rows of length S=2048. One block (256 thr) per
// row, 8 elems/thread held in registers (single gmem read + write).
// ---------------------------------------------------------------------------
__global__ __launch_bounds__(256)
void softmax2048(float* __restrict__ attn)
{
    float* p = attn + (long)blockIdx.x * Sc;
    const int tid = threadIdx.x;

    float4 v0 = ((const float4*)p)[tid];
    float4 v1 = ((const float4*)p)[tid + 256];

    float m = fmaxf(fmaxf(fmaxf(v0.x, v0.y), fmaxf(v0.z, v0.w)),
                    fmaxf(fmaxf(v1.x, v1.y), fmaxf(v1.z, v1.w)));

    __shared__ float red[256];
    red[tid] = m;
    __syncthreads();
#pragma unroll
    for (int s = 128; s > 0; s >>= 1) {
        if (tid < s) red[tid] = fmaxf(red[tid], red[tid + s]);
        __syncthreads();
    }
    const float rowmax = red[0];
    __syncthreads();

    v0.x = __expf(v0.x - rowmax); v0.y = __expf(v0.y - rowmax);
    v0.z = __expf(v0.z - rowmax); v0.w = __expf(v0.w - rowmax);
    v1.x = __expf(v1.x - rowmax); v1.y = __expf(v1.y - rowmax);
    v1.z = __expf(v1.z - rowmax); v1.w = __expf(v1.w - rowmax);

    float sum = (v0.x + v0.y) + (v0.z + v0.w) + (v1.x + v1.y) + (v1.z + v1.w);
    red[tid] = sum;
    __syncthreads();
#pragma unroll
    for (int s = 128; s > 0; s >>= 1) {
        if (tid < s) red[tid] += red[tid + s];
        __syncthreads();
    }
    const float inv = 1.0f / red[0];

    v0.x *= inv; v0.y *= inv; v0.z *= inv; v0.w *= inv;
    v1.x *= inv; v1.y *= inv; v1.z *= inv; v1.w *= inv;

    ((float4*)p)[tid]       = v0;
    ((float4*)p)[tid + 256] = v1;
}

// ---------------------------------------------------------------------------
// ctx = attn @ v per (b,h). M=S=2048, N=D=64, K=S=2048.
// BM=128, BN=64, BK=16, 256 threads, 8x4 per thread.
// Writes into merged-head layout g_ctx[b][s][h*64+d].
// ---------------------------------------------------------------------------
__global__ __launch_bounds__(256, 2)
void gemm_av(const float* __restrict__ attn, const float* __restrict__ V,
             float* __restrict__ ctx)
{
    const int z = blockIdx.z;       // b*H + h
    const int b = z / Hc;
    const int h = z % Hc;

    const float* P  = attn + (long)z * Sc * Sc;
    const float* Vv = V    + (long)z * Sc * Dc;
    float*       Cp = ctx  + (long)b * Sc * Ec + h * Dc;

    const int m0 = blockIdx.y * 128;

    __shared__ float Ps[16][128 + 4];
    __shared__ float Vs[16][64];

    const int tid = threadIdx.x;
    const int tx  = tid & 15;   // n = tx*4 .. +3
    const int ty  = tid >> 4;   // m = ty*8 .. +7

    float acc[8][4];
#pragma unroll
    for (int i = 0; i < 8; i++)
#pragma unroll
        for (int j = 0; j < 4; j++) acc[i][j] = 0.0f;

    for (int kt = 0; kt < Sc; kt += 16) {
        // P tile: 128x16 (2048 floats) = 512 float4, 2 per thread; store transposed
#pragma unroll
        for (int r = 0; r < 2; r++) {
            const int idx = tid + r * 256;      // 0..511
            const int row = idx >> 2;           // 0..127
            const int c4  = (idx & 3) * 4;      // 0,4,8,12
            float4 p = *(const float4*)(P + (long)(m0 + row) * Sc + kt + c4);
            Ps[c4 + 0][row] = p.x; Ps[c4 + 1][row] = p.y;
            Ps[c4 + 2][row] = p.z; Ps[c4 + 3][row] = p.w;
        }
        // V tile: 16x64 = 256 float4, 1 per thread
        {
            const int row = tid >> 4;
            const int c4  = (tid & 15) * 4;
            float4 v = *(const float4*)(Vv + (long)(kt + row) * Dc + c4);
            *(float4*)&Vs[row][c4] = v;
        }
        __syncthreads();

#pragma unroll
        for (int k = 0; k < 16; k++) {
            float ra[8], rb[4];
#pragma unroll
            for (int i = 0; i < 8; i++) ra[i] = Ps[k][ty * 8 + i];
#pragma unroll
            for (int j = 0; j < 4; j++) rb[j] = Vs[k][tx * 4 + j];
#pragma unroll
            for (int i = 0; i < 8; i++)
#pragma unroll
                for (int j = 0; j < 4; j++)
                    acc[i][j] = fmaf(ra[i], rb[j], acc[i][j]);
        }
        __syncthreads();
    }

#pragma unroll
    for (int i = 0; i < 8; i++) {
        const int m = m0 + ty * 8 + i;   // s
#pragma unroll
        for (int j = 0; j < 4; j++) {
            const int n = tx * 4 + j;    // d
            Cp[(long)m * Ec + n] = acc[i][j];
        }
    }
}

// ---------------------------------------------------------------------------
extern "C" void kernel_launch(void* const* d_in, const int* in_sizes, int n_in,
                              void* d_out, int out_size)
{
    const float* query = (const float*)d_in[0];
    const float* key   = (const float*)d_in[1];
    const float* value = (const float*)d_in[2];
    const float* Wq    = (const float*)d_in[3];
    const float* bq    = (const float*)d_in[4];
    const float* Wk    = (const float*)d_in[5];
    const float* bk    = (const float*)d_in[6];
    const float* Wv    = (const float*)d_in[7];
    const float* bv    = (const float*)d_in[8];
    const float* Wo    = (const float*)d_in[9];
    const float* bo    = (const float*)d_in[10];

    float* out  = (float*)d_out;
    float* attn = out + (long)Bc * Sc * Ec;   // tuple layout: out first, attn second

    float *q, *k, *v, *ctx;
    cudaGetSymbolAddress((void**)&q,   g_q);
    cudaGetSymbolAddress((void**)&k,   g_k);
    cudaGetSymbolAddress((void**)&v,   g_v);
    cudaGetSymbolAddress((void**)&ctx, g_ctx);

    const dim3 blk(256);
    const int  M = Bc * Sc;   // 4096

    // 1) Q/K/V projections -> head-split (b,h,s,d)
    const dim3 gp(Ec / 128, M / 128, 1);
    gemm128_xwT<true><<<gp, blk>>>(query, Wq, bq, q, M, Ec, Ec, 0, 0, 0, 1.0f);
    gemm128_xwT<true><<<gp, blk>>>(key,   Wk, bk, k, M, Ec, Ec, 0, 0, 0, 1.0f);
    gemm128_xwT<true><<<gp, blk>>>(value, Wv, bv, v, M, Ec, Ec, 0, 0, 0, 1.0f);

    // 2) scores = q @ k^T * D^-0.5, batched over 32 (b,h), written into attn
    const dim3 gs(Sc / 128, Sc / 128, Bc * Hc);
    gemm128_xwT<false><<<gs, blk>>>(q, k, nullptr, attn, Sc, Sc, Dc,
                                    (long)Sc * Dc, (long)Sc * Dc,
                                    (long)Sc * Sc, 0.125f);

    // 3) softmax rows, in place
    softmax2048<<<Bc * Hc * Sc, 256>>>(attn);

    // 4) ctx = attn @ v -> merged-head (b,s,E)
    const dim3 ga(1, Sc / 128, Bc * Hc);
    gemm_av<<<ga, blk>>>(attn, v, ctx);

    // 5) out = ctx @ Wo^T + bo
    gemm128_xwT<false><<<gp, blk>>>(ctx, Wo, bo, out, M, Ec, Ec, 0, 0, 0, 1.0f);
}

// round 3
// speedup vs baseline: 2.6837x; 2.6837x over previous
#include <cuda_runtime.h>
#include <cstdint>

static constexpr int Bc = 2;
static constexpr int Sc = 2048;
static constexpr int Ec = 1024;
static constexpr int Hc = 16;
static constexpr int Dc = 64;

// Scratch (__device__ globals per allocation rules)
__device__ float g_q  [(size_t)Bc * Hc * Sc * Dc];   // (b,h,s,d)
__device__ float g_k  [(size_t)Bc * Hc * Sc * Dc];   // (b,h,s,d)
__device__ float g_vT [(size_t)Bc * Hc * Dc * Sc];   // (b,h,d,s)
__device__ float g_ctx[(size_t)Bc * Sc * Ec];        // (b,s,E)

// round-to-nearest tf32 bits
__device__ __forceinline__ uint32_t tf32r(float x) {
    uint32_t u = __float_as_uint(x);
    return (u + 0x1000u) & 0xFFFFE000u;
}

// ---------------------------------------------------------------------------
// tf32 mma.sync GEMM: C = A @ B^T * scale (+bias)
// A: (M,K) row-major, B: (N,K) row-major. BM=128, BK=32.
// EPI: 0 row-major C (stride N) | 1 head-split (b,h,s,d) |
//      2 transposed head-split (b,h,d,s) | 3 merged ctx (b,s,E)
// SMEM holds fragment-order tiles so LDS is ld.shared.v4/v2 conflict-free.
// ---------------------------------------------------------------------------
template <int BN, int EPI>
__global__ __launch_bounds__(256)
void mma_gemm(const float* __restrict__ A, const float* __restrict__ Bm,
              const float* __restrict__ bias, float* __restrict__ C,
              int N, int K, long sA, long sB, long sC, float scale)
{
    constexpr int WARPS_M = (BN == 128) ? 2 : 4;
    constexpr int WARPS_N = 8 / WARPS_M;
    constexpr int WM = 128 / WARPS_M;      // 64 or 32
    constexpr int WN = BN / WARPS_N;       // 32
    constexpr int MT = WM / 16;            // 4 or 2
    constexpr int NT = WN / 8;             // 4
    constexpr int NB8 = BN / 8;
    constexpr int AF = 4096;               // A floats/stage (128*32)
    constexpr int BF = BN * 32;            // B floats/stage
    constexpr int NLB = BN / 32;           // B float4 loads per thread

    extern __shared__ uint32_t sm[];
    uint32_t* Abuf = sm;                   // 2 stages x AF
    uint32_t* Bbuf = sm + 2 * AF;          // 2 stages x BF

    const int tid  = threadIdx.x;
    const int wid  = tid >> 5;
    const int lane = tid & 31;
    const int wm   = wid % WARPS_M;
    const int wn   = wid / WARPS_M;

    A  += (long)blockIdx.z * sA;
    Bm += (long)blockIdx.z * sB;
    C  += (long)blockIdx.z * sC;
    const int m0 = blockIdx.y * 128;
    const int n0 = blockIdx.x * BN;

    // global-load geometry: each thread loads float4 at (row = tid/8 + 32i, col = c4)
    const int lrow  = tid >> 3;
    const int c4    = (tid & 7) * 4;
    const int kt_s  = c4 >> 3;             // k-step this thread's columns fall in
    const int reghi = (c4 >> 2) & 1;       // high-half-of-k bit

    const float* Ap = A  + (long)m0 * K;
    const float* Bp = Bm + (long)n0 * K;
    const int nk = K >> 5;

    float4 aR[4], bR[NLB];

    float acc[MT][NT][4];
#pragma unroll
    for (int i = 0; i < MT; i++)
#pragma unroll
        for (int j = 0; j < NT; j++)
#pragma unroll
            for (int r = 0; r < 4; r++) acc[i][j][r] = 0.0f;

    auto ldg = [&](int it) {
        const int k0 = it << 5;
#pragma unroll
        for (int i = 0; i < 4; i++)
            aR[i] = *(const float4*)(Ap + (long)(lrow + i * 32) * K + k0 + c4);
#pragma unroll
        for (int i = 0; i < NLB; i++)
            bR[i] = *(const float4*)(Bp + (long)(lrow + i * 32) * K + k0 + c4);
    };

    auto sts = [&](int s) {
        uint32_t* Asd = Abuf + s * AF;
        uint32_t* Bsd = Bbuf + s * BF;
#pragma unroll
        for (int i = 0; i < 4; i++) {
            const int row = lrow + i * 32;
            const int mt  = row >> 4;
            const int reg = ((row >> 3) & 1) + 2 * reghi;
            const int lb  = (row & 7) * 4;
            const float* v = (const float*)&aR[i];
#pragma unroll
            for (int j = 0; j < 4; j++) {
                const int ln = (lb + j) ^ kt_s;     // swizzle for STS bank spread
                Asd[((kt_s * 8 + mt) * 32 + ln) * 4 + reg] = tf32r(v[j]);
            }
        }
#pragma unroll
        for (int i = 0; i < NLB; i++) {
            const int n  = lrow + i * 32;
            const int nt = n >> 3;
            const int lb = (n & 7) * 4;
            const float* v = (const float*)&bR[i];
#pragma unroll
            for (int j = 0; j < 4; j++) {
                const int ln = (lb + j) ^ kt_s;
                Bsd[((kt_s * NB8 + nt) * 32 + ln) * 2 + reghi] = tf32r(v[j]);
            }
        }
    };

    auto compute = [&](int s) {
        const uint32_t* Asd = Abuf + s * AF;
        const uint32_t* Bsd = Bbuf + s * BF;
#pragma unroll
        for (int kt = 0; kt < 4; kt++) {
            const int lx = lane ^ kt;
            uint32_t a[MT][4], b[NT][2];
#pragma unroll
            for (int mt = 0; mt < MT; mt++) {
                uint4 v = *(const uint4*)(Asd + ((kt * 8 + wm * MT + mt) * 32 + lx) * 4);
                a[mt][0] = v.x; a[mt][1] = v.y; a[mt][2] = v.z; a[mt][3] = v.w;
            }
#pragma unroll
            for (int nt = 0; nt < NT; nt++) {
                uint2 v = *(const uint2*)(Bsd + ((kt * NB8 + wn * NT + nt) * 32 + lx) * 2);
                b[nt][0] = v.x; b[nt][1] = v.y;
            }
#pragma unroll
            for (int mt = 0; mt < MT; mt++)
#pragma unroll
                for (int nt = 0; nt < NT; nt++) {
                    float* d = acc[mt][nt];
                    asm volatile(
                        "mma.sync.aligned.m16n8k8.row.col.f32.tf32.tf32.f32 "
                        "{%0,%1,%2,%3}, {%4,%5,%6,%7}, {%8,%9}, {%0,%1,%2,%3};"
                        : "+f"(d[0]), "+f"(d[1]), "+f"(d[2]), "+f"(d[3])
                        : "r"(a[mt][0]), "r"(a[mt][1]), "r"(a[mt][2]), "r"(a[mt][3]),
                          "r"(b[nt][0]), "r"(b[nt][1]));
                }
        }
    };

    // pipeline: ldg(next) | compute(cur) | sts(next) | sync
    ldg(0);
    sts(0);
    __syncthreads();
    for (int it = 0; it < nk; it++) {
        const int s = it & 1;
        if (it + 1 < nk) ldg(it + 1);
        compute(s);
        if (it + 1 < nk) { sts(1 - s); __syncthreads(); }
    }

    // epilogue: straight from fragments
    const int g  = lane >> 2;
    const int t2 = (lane & 3) * 2;
#pragma unroll
    for (int mt = 0; mt < MT; mt++) {
#pragma unroll
        for (int nt = 0; nt < NT; nt++) {
            const int row = m0 + wm * WM + mt * 16 + g;
            const int col = n0 + wn * WN + nt * 8 + t2;
            float c0 = acc[mt][nt][0] * scale;
            float c1 = acc[mt][nt][1] * scale;
            float c2 = acc[mt][nt][2] * scale;
            float c3 = acc[mt][nt][3] * scale;
            if (bias) {
                const float b0 = bias[col], b1 = bias[col + 1];
                c0 += b0; c1 += b1; c2 += b0; c3 += b1;
            }
            if (EPI == 0) {
                *(float2*)(C + (long)row * N + col)       = make_float2(c0, c1);
                *(float2*)(C + (long)(row + 8) * N + col) = make_float2(c2, c3);
            } else if (EPI == 1) {
                // (b,h,s,d)
                const int b = row >> 11, si = row & 2047, h = col >> 6, d = col & 63;
                float* p = C + (((long)(b * Hc + h) * Sc + si) * Dc + d);
                *(float2*)p                 = make_float2(c0, c1);
                *(float2*)(p + 8 * Dc)      = make_float2(c2, c3);
            } else if (EPI == 2) {
                // (b,h,d,s): cols->d (stride Sc), rows->s
                const int b = row >> 11, si = row & 2047, h = col >> 6, d = col & 63;
                float* p = C + (((long)(b * Hc + h) * Dc + d) * Sc + si);
                p[0]      = c0;  p[Sc]      = c1;
                p[8]      = c2;  p[Sc + 8]  = c3;
            } else {
                // (b,s,E) merged heads; z = b*H + h, col in 0..63
                const int z = blockIdx.z, b = z >> 4, h = z & 15;
                float* p = C + (long)b * Sc * Ec + (long)row * Ec + h * Dc + col;
                *(float2*)p            = make_float2(c0, c1);
                *(float2*)(p + 8 * Ec) = make_float2(c2, c3);
            }
        }
    }
}

// ---------------------------------------------------------------------------
// Row softmax in place: rows of 2048, one 256-thread block per row.
// ---------------------------------------------------------------------------
__global__ __launch_bounds__(256)
void softmax2048(float* __restrict__ attn)
{
    float* p = attn + (long)blockIdx.x * Sc;
    const int tid = threadIdx.x;

    float4 v0 = ((const float4*)p)[tid];
    float4 v1 = ((const float4*)p)[tid + 256];

    float m = fmaxf(fmaxf(fmaxf(v0.x, v0.y), fmaxf(v0.z, v0.w)),
                    fmaxf(fmaxf(v1.x, v1.y), fmaxf(v1.z, v1.w)));

    __shared__ float red[256];
    red[tid] = m;
    __syncthreads();
#pragma unroll
    for (int s = 128; s > 0; s >>= 1) {
        if (tid < s) red[tid] = fmaxf(red[tid], red[tid + s]);
        __syncthreads();
    }
    const float rowmax = red[0];
    __syncthreads();

    v0.x = __expf(v0.x - rowmax); v0.y = __expf(v0.y - rowmax);
    v0.z = __expf(v0.z - rowmax); v0.w = __expf(v0.w - rowmax);
    v1.x = __expf(v1.x - rowmax); v1.y = __expf(v1.y - rowmax);
    v1.z = __expf(v1.z - rowmax); v1.w = __expf(v1.w - rowmax);

    float sum = (v0.x + v0.y) + (v0.z + v0.w) + (v1.x + v1.y) + (v1.z + v1.w);
    red[tid] = sum;
    __syncthreads();
#pragma unroll
    for (int s = 128; s > 0; s >>= 1) {
        if (tid < s) red[tid] += red[tid + s];
        __syncthreads();
    }
    const float inv = 1.0f / red[0];

    v0.x *= inv; v0.y *= inv; v0.z *= inv; v0.w *= inv;
    v1.x *= inv; v1.y *= inv; v1.z *= inv; v1.w *= inv;

    ((float4*)p)[tid]       = v0;
    ((float4*)p)[tid + 256] = v1;
}

// ---------------------------------------------------------------------------
extern "C" void kernel_launch(void* const* d_in, const int* in_sizes, int n_in,
                              void* d_out, int out_size)
{
    const float* query = (const float*)d_in[0];
    const float* key   = (const float*)d_in[1];
    const float* value = (const float*)d_in[2];
    const float* Wq    = (const float*)d_in[3];
    const float* bq    = (const float*)d_in[4];
    const float* Wk    = (const float*)d_in[5];
    const float* bk    = (const float*)d_in[6];
    const float* Wv    = (const float*)d_in[7];
    const float* bv    = (const float*)d_in[8];
    const float* Wo    = (const float*)d_in[9];
    const float* bo    = (const float*)d_in[10];

    float* out  = (float*)d_out;
    float* attn = out + (long)Bc * Sc * Ec;

    float *q, *k, *vT, *ctx;
    cudaGetSymbolAddress((void**)&q,   g_q);
    cudaGetSymbolAddress((void**)&k,   g_k);
    cudaGetSymbolAddress((void**)&vT,  g_vT);
    cudaGetSymbolAddress((void**)&ctx, g_ctx);

    constexpr int SMEM128 = (2 * 4096 + 2 * 128 * 32) * 4;  // 65536
    constexpr int SMEM64  = (2 * 4096 + 2 *  64 * 32) * 4;  // 49152

    cudaFuncSetAttribute((const void*)mma_gemm<128, 0>, cudaFuncAttributeMaxDynamicSharedMemorySize, SMEM128);
    cudaFuncSetAttribute((const void*)mma_gemm<128, 1>, cudaFuncAttributeMaxDynamicSharedMemorySize, SMEM128);
    cudaFuncSetAttribute((const void*)mma_gemm<128, 2>, cudaFuncAttributeMaxDynamicSharedMemorySize, SMEM128);
    cudaFuncSetAttribute((const void*)mma_gemm<64, 3>,  cudaFuncAttributeMaxDynamicSharedMemorySize, SMEM64);

    const dim3 blk(256);
    const dim3 gp(Ec / 128, (Bc * Sc) / 128, 1);     // 8 x 32
    const dim3 gqk(Sc / 128, Sc / 128, Bc * Hc);     // 16 x 16 x 32
    const dim3 gav(1, Sc / 128, Bc * Hc);            // 1 x 16 x 32

    // 1) projections
    mma_gemm<128, 1><<<gp, blk, SMEM128>>>(query, Wq, bq, q,  Ec, Ec, 0, 0, 0, 1.0f);
    mma_gemm<128, 1><<<gp, blk, SMEM128>>>(key,   Wk, bk, k,  Ec, Ec, 0, 0, 0, 1.0f);
    mma_gemm<128, 2><<<gp, blk, SMEM128>>>(value, Wv, bv, vT, Ec, Ec, 0, 0, 0, 1.0f);

    // 2) scores = q @ k^T * D^-0.5 -> attn
    mma_gemm<128, 0><<<gqk, blk, SMEM128>>>(q, k, nullptr, attn, Sc, Dc,
                                            (long)Sc * Dc, (long)Sc * Dc, (long)Sc * Sc, 0.125f);

    // 3) softmax in place
    softmax2048<<<Bc * Hc * Sc, 256>>>(attn);

    // 4) ctx = attn @ vT^T -> merged (b,s,E)
    mma_gemm<64, 3><<<gav, blk, SMEM64>>>(attn, vT, nullptr, ctx, Dc, Sc,
                                          (long)Sc * Sc, (long)Sc * Dc, 0, 1.0f);

    // 5) out = ctx @ Wo^T + bo
    mma_gemm<128, 0><<<gp, blk, SMEM128>>>(ctx, Wo, bo, out, Ec, Ec, 0, 0, 0, 1.0f);
}